// round 16
// baseline (speedup 1.0000x reference)
#include <cuda_runtime.h>
#include <cuda_bf16.h>

#define NN 16384      // nodes/edges (and bond_n rows A = 16384)
#define DD 128        // emb dim
// Only layer i = 2 matters: the reference loop does not feed h back.

// Scratch (device globals — zero-initialized at module load)
__device__ float g_colw[NN];
__device__ float g_hn[(size_t)NN * DD];      // 8 MB
__device__ float g_mpartT[DD][256];          // m partials, contiguous per d
__device__ float g_mm[DD];
__device__ unsigned g_cnt;                   // k_m last-block counter (self-resets)

// ---------------------------------------------------------------------------
// k_fused, 384 blocks (2/SM -> 296 wave-1 slots; the rest launch as GEMM
// blocks retire — HW work-stealing replaces retired GEMM blocks with fresh
// stream blocks, doubling streaming warps in the long phase):
//   bids [0,128):    GEMM h_n = relu(cat @ Wi_w[2].T + b), 128 rows each.
//   bids [128,384):  column-sum, 64-col slice each (full rows, direct write).
// No atomics on data; deterministic.
// ---------------------------------------------------------------------------
__global__ void __launch_bounds__(256) k_fused(
    const float* __restrict__ bn,
    const int* __restrict__ x, const int* __restrict__ ea,
    const float* __restrict__ aemb, const float* __restrict__ bemb,
    const float* __restrict__ Wi_w2, const float* __restrict__ Wi_b2)
{
    extern __shared__ float sm[];
    const int tid = threadIdx.x;
    const int bid = blockIdx.x;

    if (bid >= 128) {
        // ---------------- column-sum path: 64-col slice, all rows ----------
        const int colBase = (bid - 128) * 64;
        const int c4     = tid & 15;          // float4-column within slice
        const int rowoff = tid >> 4;          // 0..15, stride 16 rows
        const float* base = bn + (size_t)rowoff * NN + colBase + c4 * 4;
        float4 a0 = {0,0,0,0}, a1 = {0,0,0,0}, a2 = {0,0,0,0}, a3 = {0,0,0,0};
        for (int i = 0; i < 1024; i += 16) {
#pragma unroll
            for (int u = 0; u < 16; u++) {
                float4 v = __ldcs((const float4*)(base + (size_t)(i + u) * 16 * NN));
                float4& a = (u & 3) == 0 ? a0 : (u & 3) == 1 ? a1 : (u & 3) == 2 ? a2 : a3;
                a.x += v.x; a.y += v.y; a.z += v.z; a.w += v.w;
            }
        }
        // cross-rowoff reduce: part[16][64]
        float* part = sm;
        part[rowoff * 64 + c4 * 4 + 0] = a0.x + a1.x + a2.x + a3.x;
        part[rowoff * 64 + c4 * 4 + 1] = a0.y + a1.y + a2.y + a3.y;
        part[rowoff * 64 + c4 * 4 + 2] = a0.z + a1.z + a2.z + a3.z;
        part[rowoff * 64 + c4 * 4 + 3] = a0.w + a1.w + a2.w + a3.w;
        __syncthreads();
        if (tid < 64) {
            float s = 0.f;
#pragma unroll
            for (int w = 0; w < 16; w++) s += part[w * 64 + tid];
            g_colw[colBase + tid] = s;
        }
        return;
    }

    // ---------------- GEMM path (bids 0..127) ----------------
    float* w_s   = sm;                 // [64][129]  = 33,024 B (per-k chunk)
    float* cat_s = sm + 64 * 129;      // [128][64]  = 32,768 B

    __shared__ float bias_s[128];
    __shared__ int xi0[128], xi1[128], ei0[128], ei1[128];

    const int rowBase = bid * 128;

    if (tid < 128) {
        bias_s[tid] = Wi_b2[tid];
        int r = rowBase + tid;
        xi0[tid] = x[2 * r];  xi1[tid] = x[2 * r + 1];
        ei0[tid] = ea[2 * r]; ei1[tid] = ea[2 * r + 1];
    }
    __syncthreads();

    const int tx = tid & 15, ty = tid >> 4;
    float acc[8][8];
#pragma unroll
    for (int i = 0; i < 8; i++)
#pragma unroll
        for (int j = 0; j < 8; j++) acc[i][j] = 0.f;

    for (int kc = 0; kc < 256; kc += 64) {
        // stage W chunk transposed: w_s[kk][d] = Wi_w2[d*256 + kc + kk]
        for (int idx = tid; idx < 8192; idx += 256) {
            int d = idx >> 6, kk = idx & 63;
            w_s[kk * 129 + d] = Wi_w2[d * 256 + kc + kk];
        }
        // stage cat chunk: cat_s[row][kloc] (embedding pair-sum gathers)
        const bool atom = (kc < 128);
        const float* emb = atom ? aemb : bemb;
        for (int idx = tid; idx < 2048; idx += 256) {
            int row  = idx >> 4;
            int kloc = (idx & 15) * 4;
            int i0 = atom ? xi0[row] : ei0[row];
            int i1 = atom ? xi1[row] : ei1[row];
            int ko = atom ? (kc + kloc) : (kc - 128 + kloc);
            float4 v0 = *(const float4*)(emb + i0 * 128 + ko);
            float4 v1 = *(const float4*)(emb + i1 * 128 + ko);
            float4 s;
            s.x = v0.x + v1.x; s.y = v0.y + v1.y;
            s.z = v0.z + v1.z; s.w = v0.w + v1.w;
            *(float4*)(cat_s + row * 64 + kloc) = s;
        }
        __syncthreads();

#pragma unroll 8
        for (int kk = 0; kk < 64; kk++) {
            const float* wr = w_s + kk * 129;
            float b[8], a[8];
#pragma unroll
            for (int j = 0; j < 8; j++) b[j] = wr[tx + 16 * j];
#pragma unroll
            for (int i = 0; i < 8; i++) a[i] = cat_s[(ty + 16 * i) * 64 + kk];
#pragma unroll
            for (int i = 0; i < 8; i++)
#pragma unroll
                for (int j = 0; j < 8; j++)
                    acc[i][j] = fmaf(a[i], b[j], acc[i][j]);
        }
        __syncthreads();
    }

    // epilogue: bias + relu -> g_hn
#pragma unroll
    for (int i = 0; i < 8; i++) {
        int r = ty + 16 * i;
#pragma unroll
        for (int j = 0; j < 8; j++) {
            int d = tx + 16 * j;
            float v = acc[i][j] + bias_s[d];
            g_hn[(size_t)(rowBase + r) * 128 + d] = v > 0.f ? v : 0.f;
        }
    }
}

// ---------------------------------------------------------------------------
// k_m (R13 verbatim): 256 blocks, each owns 64 rows. m partial (unroll 16)
// -> g_mpartT[d][b] (transposed, contiguous per d). Last block: 64
// consecutive float4 loads per d + mm = m @ Wm^T + b. Counter self-resets.
// ---------------------------------------------------------------------------
__global__ void __launch_bounds__(256) k_m(const float* __restrict__ Wm_w2,
                                           const float* __restrict__ Wm_b2) {
    __shared__ float colw_s[64];
    __shared__ float red[256];
    __shared__ float ms[128];
    __shared__ bool last;

    const int b = blockIdx.x, tid = threadIdx.x;
    const int d = tid & 127, half = tid >> 7;
    const int rowBase = b * 64;

    if (tid < 64) colw_s[tid] = g_colw[rowBase + tid];
    __syncthreads();

    // m partial: rows [rowBase + half*32, +32)
    {
        float p = 0.f;
#pragma unroll 16
        for (int r = 0; r < 32; r++) {
            int row = half * 32 + r;
            p = fmaf(colw_s[row], g_hn[(size_t)(rowBase + row) * DD + d], p);
        }
        red[tid] = p;
    }
    __syncthreads();
    if (tid < 128) g_mpartT[tid][b] = red[tid] + red[tid + 128];
    __threadfence();
    if (tid == 0) last = (atomicAdd(&g_cnt, 1u) == 255u);
    __syncthreads();

    if (last) {
        if (tid < 128) {
            const float4* mp = (const float4*)g_mpartT[tid];
            float s = 0.f;
#pragma unroll 32
            for (int w = 0; w < 64; w++) {
                float4 v = __ldcg(mp + w);
                s += v.x + v.y + v.z + v.w;
            }
            ms[tid] = s;
        }
        __syncthreads();
        if (tid < 128) {
            float s = Wm_b2[tid];
            const float* row = Wm_w2 + tid * 128;
#pragma unroll 8
            for (int k = 0; k < 128; k++) s = fmaf(ms[k], __ldg(row + k), s);
            g_mm[tid] = s;
        }
        if (tid == 0) g_cnt = 0u;   // reset for next graph replay
    }
}

// ---------------------------------------------------------------------------
// k_out, 2048 blocks: out = relu(h_n + mm[broadcast])
// ---------------------------------------------------------------------------
__global__ void __launch_bounds__(256) k_out(float* __restrict__ out) {
    __shared__ float mm[128];
    if (threadIdx.x < 128) mm[threadIdx.x] = g_mm[threadIdx.x];
    __syncthreads();
    size_t i = (size_t)blockIdx.x * 256 + threadIdx.x;   // float4 index
    float4 v = *(const float4*)(g_hn + i * 4);
    int d0 = (int)((i * 4) & 127);
    v.x = fmaxf(v.x + mm[d0 + 0], 0.f);
    v.y = fmaxf(v.y + mm[d0 + 1], 0.f);
    v.z = fmaxf(v.z + mm[d0 + 2], 0.f);
    v.w = fmaxf(v.w + mm[d0 + 3], 0.f);
    *((float4*)out + i) = v;
}

// ---------------------------------------------------------------------------
extern "C" void kernel_launch(void* const* d_in, const int* in_sizes, int n_in,
                              void* d_out, int out_size) {
    const int*   x    = (const int*)d_in[0];
    const int*   ea   = (const int*)d_in[1];
    const float* bn   = (const float*)d_in[2];
    const float* aemb = (const float*)d_in[3];
    const float* bemb = (const float*)d_in[4];
    const float* Wi_w = (const float*)d_in[5];
    const float* Wi_b = (const float*)d_in[6];
    const float* Wm_w = (const float*)d_in[7];
    const float* Wm_b = (const float*)d_in[8];

    // Only the last layer (i = 2) affects the output.
    const float* Wi_w2 = Wi_w + 2 * 128 * 256;
    const float* Wi_b2 = Wi_b + 2 * 128;
    const float* Wm_w2 = Wm_w + 2 * 128 * 128;
    const float* Wm_b2 = Wm_b + 2 * 128;

    const int smem = (64 * 129 + 128 * 64) * (int)sizeof(float);  // 65,792 B
    static bool attr_set = false;
    if (!attr_set) {
        cudaFuncSetAttribute(k_fused, cudaFuncAttributeMaxDynamicSharedMemorySize, smem);
        attr_set = true;
    }

    k_fused<<<384, 256, smem>>>(bn, x, ea, aemb, bemb, Wi_w2, Wi_b2);
    k_m<<<256, 256>>>(Wm_w2, Wm_b2);
    k_out<<<2048, 256>>>((float*)d_out);
}

// round 17
// speedup vs baseline: 1.0007x; 1.0007x over previous
#include <cuda_runtime.h>
#include <cuda_bf16.h>

#define NN 16384      // nodes/edges (and bond_n rows A = 16384)
#define DD 128        // emb dim
// Only layer i = 2 matters: the reference loop does not feed h back.

// Scratch (device globals — zero-initialized at module load)
__device__ float g_hn[(size_t)NN * DD];      // 8 MB
__device__ float g_mpartT[DD][256];          // m partials, contiguous per d
__device__ float g_mm[DD];
__device__ unsigned g_hflag[128];            // h_n-ready flags (k_out resets)
__device__ unsigned g_cnt;                   // colsum last-block counter (self-resets)

// ---------------------------------------------------------------------------
// k_fused, 384 blocks (2/SM -> 296 wave-1 slots; retiring GEMM blocks are
// replaced by fresh stream blocks via HW work-stealing):
//   bids [0,128):    GEMM h_n = relu(cat @ Wi_w[2].T + b) -> g_hn, set flag.
//   bids [128,384):  column-sum of a 64-col slice (colw stays in SMEM),
//                    wait own GEMM flag (set ~140us earlier -> free),
//                    m-partial over own 64 h_n rows -> g_mpartT[d][b];
//                    LAST colsum block reduces partials + mm GEMV -> g_mm.
// No data atomics; deterministic.
// ---------------------------------------------------------------------------
__global__ void __launch_bounds__(256) k_fused(
    const float* __restrict__ bn,
    const int* __restrict__ x, const int* __restrict__ ea,
    const float* __restrict__ aemb, const float* __restrict__ bemb,
    const float* __restrict__ Wi_w2, const float* __restrict__ Wi_b2,
    const float* __restrict__ Wm_w2, const float* __restrict__ Wm_b2)
{
    extern __shared__ float sm[];
    const int tid = threadIdx.x;
    const int bid = blockIdx.x;

    if (bid >= 128) {
        // ---------------- column-sum path: 64-col slice, all rows ----------
        __shared__ float colw_s[64];
        __shared__ float red[256];
        __shared__ float ms[128];
        __shared__ bool last;

        const int colBase = (bid - 128) * 64;
        const int c4     = tid & 15;          // float4-column within slice
        const int rowoff = tid >> 4;          // 0..15, stride 16 rows
        const float* base = bn + (size_t)rowoff * NN + colBase + c4 * 4;
        float4 a0 = {0,0,0,0}, a1 = {0,0,0,0}, a2 = {0,0,0,0}, a3 = {0,0,0,0};
        for (int i = 0; i < 1024; i += 16) {
#pragma unroll
            for (int u = 0; u < 16; u++) {
                float4 v = __ldcs((const float4*)(base + (size_t)(i + u) * 16 * NN));
                float4& a = (u & 3) == 0 ? a0 : (u & 3) == 1 ? a1 : (u & 3) == 2 ? a2 : a3;
                a.x += v.x; a.y += v.y; a.z += v.z; a.w += v.w;
            }
        }
        // cross-rowoff reduce: part[16][64] in dynamic smem
        float* part = sm;
        part[rowoff * 64 + c4 * 4 + 0] = a0.x + a1.x + a2.x + a3.x;
        part[rowoff * 64 + c4 * 4 + 1] = a0.y + a1.y + a2.y + a3.y;
        part[rowoff * 64 + c4 * 4 + 2] = a0.z + a1.z + a2.z + a3.z;
        part[rowoff * 64 + c4 * 4 + 3] = a0.w + a1.w + a2.w + a3.w;
        __syncthreads();
        if (tid < 64) {
            float s = 0.f;
#pragma unroll
            for (int w = 0; w < 16; w++) s += part[w * 64 + tid];
            colw_s[tid] = s;
        }
        __syncthreads();

        // wait for the GEMM block covering rows [colBase, +64) — set long ago
        if (tid == 0) {
            volatile unsigned* f = &g_hflag[colBase >> 7];
            while (*f == 0u) __nanosleep(64);
        }
        __syncthreads();
        __threadfence();

        // m-partial: p[d] = sum_{r<64} colw[r] * h_n[colBase+r][d]
        {
            const float* hn = g_hn + (size_t)colBase * 128;
            const int d = tid & 127, half = tid >> 7;
            float p = 0.f;
#pragma unroll 16
            for (int r = 0; r < 32; r++) {
                int row = half * 32 + r;
                p = fmaf(colw_s[row], __ldcg(&hn[row * 128 + d]), p);
            }
            red[tid] = p;
        }
        __syncthreads();
        if (tid < 128) g_mpartT[tid][bid - 128] = red[tid] + red[tid + 128];
        __threadfence();
        if (tid == 0) last = (atomicAdd(&g_cnt, 1u) == 255u);
        __syncthreads();

        if (last) {
            // reduce 256 contiguous partials per d, then mm = m @ Wm^T + b
            if (tid < 128) {
                const float4* mp = (const float4*)g_mpartT[tid];
                float s = 0.f;
#pragma unroll 32
                for (int w = 0; w < 64; w++) {
                    float4 v = __ldcg(mp + w);
                    s += v.x + v.y + v.z + v.w;
                }
                ms[tid] = s;
            }
            __syncthreads();
            if (tid < 128) {
                float s = Wm_b2[tid];
                const float* row = Wm_w2 + tid * 128;
#pragma unroll 8
                for (int k = 0; k < 128; k++) s = fmaf(ms[k], __ldg(row + k), s);
                g_mm[tid] = s;
            }
            if (tid == 0) g_cnt = 0u;   // reset for next graph replay
        }
        return;
    }

    // ---------------- GEMM path (bids 0..127) ----------------
    float* w_s   = sm;                 // [64][129]  = 33,024 B (per-k chunk)
    float* cat_s = sm + 64 * 129;      // [128][64]  = 32,768 B

    __shared__ float bias_s[128];
    __shared__ int xi0[128], xi1[128], ei0[128], ei1[128];

    const int rowBase = bid * 128;

    if (tid < 128) {
        bias_s[tid] = Wi_b2[tid];
        int r = rowBase + tid;
        xi0[tid] = x[2 * r];  xi1[tid] = x[2 * r + 1];
        ei0[tid] = ea[2 * r]; ei1[tid] = ea[2 * r + 1];
    }
    __syncthreads();

    const int tx = tid & 15, ty = tid >> 4;
    float acc[8][8];
#pragma unroll
    for (int i = 0; i < 8; i++)
#pragma unroll
        for (int j = 0; j < 8; j++) acc[i][j] = 0.f;

    for (int kc = 0; kc < 256; kc += 64) {
        // stage W chunk transposed: w_s[kk][d] = Wi_w2[d*256 + kc + kk]
        for (int idx = tid; idx < 8192; idx += 256) {
            int d = idx >> 6, kk = idx & 63;
            w_s[kk * 129 + d] = Wi_w2[d * 256 + kc + kk];
        }
        // stage cat chunk: cat_s[row][kloc] (embedding pair-sum gathers)
        const bool atom = (kc < 128);
        const float* emb = atom ? aemb : bemb;
        for (int idx = tid; idx < 2048; idx += 256) {
            int row  = idx >> 4;
            int kloc = (idx & 15) * 4;
            int i0 = atom ? xi0[row] : ei0[row];
            int i1 = atom ? xi1[row] : ei1[row];
            int ko = atom ? (kc + kloc) : (kc - 128 + kloc);
            float4 v0 = *(const float4*)(emb + i0 * 128 + ko);
            float4 v1 = *(const float4*)(emb + i1 * 128 + ko);
            float4 s;
            s.x = v0.x + v1.x; s.y = v0.y + v1.y;
            s.z = v0.z + v1.z; s.w = v0.w + v1.w;
            *(float4*)(cat_s + row * 64 + kloc) = s;
        }
        __syncthreads();

#pragma unroll 8
        for (int kk = 0; kk < 64; kk++) {
            const float* wr = w_s + kk * 129;
            float b[8], a[8];
#pragma unroll
            for (int j = 0; j < 8; j++) b[j] = wr[tx + 16 * j];
#pragma unroll
            for (int i = 0; i < 8; i++) a[i] = cat_s[(ty + 16 * i) * 64 + kk];
#pragma unroll
            for (int i = 0; i < 8; i++)
#pragma unroll
                for (int j = 0; j < 8; j++)
                    acc[i][j] = fmaf(a[i], b[j], acc[i][j]);
        }
        __syncthreads();
    }

    // epilogue: bias + relu -> g_hn, then release flag
#pragma unroll
    for (int i = 0; i < 8; i++) {
        int r = ty + 16 * i;
#pragma unroll
        for (int j = 0; j < 8; j++) {
            int d = tx + 16 * j;
            float v = acc[i][j] + bias_s[d];
            g_hn[(size_t)(rowBase + r) * 128 + d] = v > 0.f ? v : 0.f;
        }
    }
    __threadfence();                    // release h_n stores
    __syncthreads();
    if (tid == 0) *((volatile unsigned*)&g_hflag[bid]) = 1u;
}

// ---------------------------------------------------------------------------
// k_out, 2048 blocks: out = relu(h_n + mm[broadcast]).
// Block 0 resets g_hflag for the next graph replay.
// ---------------------------------------------------------------------------
__global__ void __launch_bounds__(256) k_out(float* __restrict__ out) {
    __shared__ float mm[128];
    if (threadIdx.x < 128) mm[threadIdx.x] = g_mm[threadIdx.x];
    __syncthreads();

    if (blockIdx.x == 0 && threadIdx.x < 128) g_hflag[threadIdx.x] = 0u;

    size_t i = (size_t)blockIdx.x * 256 + threadIdx.x;   // float4 index
    float4 v = *(const float4*)(g_hn + i * 4);
    int d0 = (int)((i * 4) & 127);
    v.x = fmaxf(v.x + mm[d0 + 0], 0.f);
    v.y = fmaxf(v.y + mm[d0 + 1], 0.f);
    v.z = fmaxf(v.z + mm[d0 + 2], 0.f);
    v.w = fmaxf(v.w + mm[d0 + 3], 0.f);
    *((float4*)out + i) = v;
}

// ---------------------------------------------------------------------------
extern "C" void kernel_launch(void* const* d_in, const int* in_sizes, int n_in,
                              void* d_out, int out_size) {
    const int*   x    = (const int*)d_in[0];
    const int*   ea   = (const int*)d_in[1];
    const float* bn   = (const float*)d_in[2];
    const float* aemb = (const float*)d_in[3];
    const float* bemb = (const float*)d_in[4];
    const float* Wi_w = (const float*)d_in[5];
    const float* Wi_b = (const float*)d_in[6];
    const float* Wm_w = (const float*)d_in[7];
    const float* Wm_b = (const float*)d_in[8];

    // Only the last layer (i = 2) affects the output.
    const float* Wi_w2 = Wi_w + 2 * 128 * 256;
    const float* Wi_b2 = Wi_b + 2 * 128;
    const float* Wm_w2 = Wm_w + 2 * 128 * 128;
    const float* Wm_b2 = Wm_b + 2 * 128;

    const int smem = (64 * 129 + 128 * 64) * (int)sizeof(float);  // 65,792 B
    static bool attr_set = false;
    if (!attr_set) {
        cudaFuncSetAttribute(k_fused, cudaFuncAttributeMaxDynamicSharedMemorySize, smem);
        attr_set = true;
    }

    k_fused<<<384, 256, smem>>>(bn, x, ea, aemb, bemb,
                                Wi_w2, Wi_b2, Wm_w2, Wm_b2);
    k_out<<<2048, 256>>>((float*)d_out);
}